// round 7
// baseline (speedup 1.0000x reference)
#include <cuda_runtime.h>

// NF4 blockwise quant-dequant (blocksize 512).
// One warp per 512-element quant block; R7: each warp processes QPW=4
// consecutive blocks with a 2-deep register pipeline (prefetch block b+1's
// loads before computing block b) so every warp keeps 4 LDG.128 in flight
// during the reduce/classify/store tail. R6 ncu showed nothing saturated
// (DRAM 67%, L1 49%, issue 34%) -> latency-bound; this doubles outstanding
// load bytes per SM.

#define NW   8    // warps per CTA
#define QPW  4    // quant blocks per warp (pipelined)

// NF4 codebook (exact bitsandbytes constants)
#define C0  (-1.0f)
#define C1  (-0.6961928009986877f)
#define C2  (-0.5250730514526367f)
#define C3  (-0.39491748809814453f)
#define C4  (-0.28444138169288635f)
#define C5  (-0.18477343022823334f)
#define C6  (-0.09105003625154495f)
#define C7  (0.0f)
#define C8  (0.07958029955625534f)
#define C9  (0.16093020141124725f)
#define C10 (0.24611230194568634f)
#define C11 (0.33791524171829224f)
#define C12 (0.4407098591327667f)
#define C13 (0.5626170039176941f)
#define C14 (0.7229568362236023f)
#define C15 (1.0f)
// Decision boundaries: exact fp32 midpoints (folded at compile time, RN)
#define M0  ((C0  + C1 ) * 0.5f)
#define M1  ((C1  + C2 ) * 0.5f)
#define M2  ((C2  + C3 ) * 0.5f)
#define M3  ((C3  + C4 ) * 0.5f)
#define M4  ((C4  + C5 ) * 0.5f)
#define M5  ((C5  + C6 ) * 0.5f)
#define M6  ((C6  + C7 ) * 0.5f)
#define M7  ((C7  + C8 ) * 0.5f)
#define M8  ((C8  + C9 ) * 0.5f)
#define M9  ((C9  + C10) * 0.5f)
#define M10 ((C10 + C11) * 0.5f)
#define M11 ((C11 + C12) * 0.5f)
#define M12 ((C12 + C13) * 0.5f)
#define M13 ((C13 + C14) * 0.5f)
#define M14 ((C14 + C15) * 0.5f)
// "No boundary here" sentinel: huge finite fp32 (never exceeded by any x).
#define SENT (3.0e38f)

// Bucket k covers xn in [k/16 - 1, (k+1)/16 - 1); width 1/16 < min boundary
// gap 0.0805 => at most one boundary per bucket.
// tbl[k] = { threshold (or SENT), codebook value at bucket start };
// value above the threshold == vlo of bucket k+1 (index j = k+1).
__device__ const float2 g_tbl[32] = {
    {SENT, C0 }, {SENT, C0 }, {M0,   C0 }, {SENT, C1 },
    {SENT, C1 }, {SENT, C1 }, {M1,   C1 }, {SENT, C2 },
    {M2,   C2 }, {SENT, C3 }, {M3,   C3 }, {SENT, C4 },
    {M4,   C4 }, {M5,   C5 }, {SENT, C6 }, {M6,   C6 },
    {M7,   C7 }, {M8,   C8 }, {SENT, C9 }, {M9,   C9 },
    {M10,  C10}, {SENT, C11}, {M11,  C11}, {SENT, C12},
    {M12,  C12}, {SENT, C13}, {M13,  C13}, {SENT, C14},
    {SENT, C14}, {M14,  C14}, {SENT, C15}, {SENT, C15}
};

// Reduce + classify + store one 512-elem block held in v[4] (16 elems/lane).
__device__ __forceinline__ void process_block(
    const float4 v[4], float4* __restrict__ o4, int lane, float2 te) {
    float m = 0.0f;
    #pragma unroll
    for (int i = 0; i < 4; i++) {
        m = fmaxf(m, fabsf(v[i].x));
        m = fmaxf(m, fabsf(v[i].y));
        m = fmaxf(m, fabsf(v[i].z));
        m = fmaxf(m, fabsf(v[i].w));
    }
    #pragma unroll
    for (int s = 16; s; s >>= 1)
        m = fmaxf(m, __shfl_xor_sync(0xffffffffu, m, s));

    float absmax = m;
    float scale  = (absmax == 0.0f) ? 1.0f : absmax;
    float s16    = __frcp_rn(scale) * 16.0f;   // bucketing only; edge-tolerant
    float thr_s  = te.x * scale;    // x > thr*scale  ~  x/scale > thr
    float vlo_s  = te.y * absmax;   // same RN mul as reference NF4[idx]*absmax

    #pragma unroll
    for (int i = 0; i < 4; i++) {
        float4 r;
        #pragma unroll
        for (int e = 0; e < 4; e++) {
            float xv = (&v[i].x)[e];
            float kf = fmaf(xv, s16, 16.0f);   // bucket in [0,32]
            int k = min((int)kf, 31);          // trunc; -eps -> 0
            float t = __shfl_sync(0xffffffffu, thr_s, k);
            int j = k + ((xv > t) ? 1 : 0);    // above boundary -> next vlo
            (&r.x)[e] = __shfl_sync(0xffffffffu, vlo_s, j);
        }
        __stcs(&o4[i * 32 + lane], r);
    }
}

__global__ __launch_bounds__(NW * 32) void nf4_qdq_kernel(
    const float* __restrict__ x, float* __restrict__ out, long long n_qb) {
    int warp = threadIdx.x >> 5;
    int lane = threadIdx.x & 31;
    long long qb0 = ((long long)blockIdx.x * NW + warp) * QPW;
    if (qb0 >= n_qb) return;   // warp-uniform; no barriers anywhere

    float2 te = g_tbl[lane];   // per-lane bucket entry, one 8B coalesced load

    const float4* __restrict__ in4 = (const float4*)x   + qb0 * 128;
    float4*       __restrict__ o4  = (float4*)      out + qb0 * 128;

    if (qb0 + QPW <= n_qb) {
        // Main path: 2-deep register pipeline across QPW blocks.
        float4 v[4], w[4];
        #pragma unroll
        for (int i = 0; i < 4; i++) v[i] = __ldcs(&in4[i * 32 + lane]);

        #pragma unroll
        for (int b = 0; b < QPW; b++) {
            if (b + 1 < QPW) {   // prefetch next block before computing current
                const float4* nxt = in4 + (b + 1) * 128;
                #pragma unroll
                for (int i = 0; i < 4; i++) w[i] = __ldcs(&nxt[i * 32 + lane]);
            }
            process_block(v, o4 + b * 128, lane, te);
            #pragma unroll
            for (int i = 0; i < 4; i++) v[i] = w[i];   // renamed away by unroll
        }
    } else {
        // Tail path (n_qb not divisible by NW*QPW): one block at a time.
        for (int b = 0; b < QPW && qb0 + b < n_qb; b++) {
            float4 v[4];
            const float4* p = in4 + b * 128;
            #pragma unroll
            for (int i = 0; i < 4; i++) v[i] = __ldcs(&p[i * 32 + lane]);
            process_block(v, o4 + b * 128, lane, te);
        }
    }
}

extern "C" void kernel_launch(void* const* d_in, const int* in_sizes, int n_in,
                              void* d_out, int out_size) {
    const float* x = (const float*)d_in[0];
    float* out = (float*)d_out;
    long long n = (long long)in_sizes[0];
    long long n_qb = n / 512;                       // n is a multiple of 512
    long long per_cta = (long long)NW * QPW;        // 32 blocks per CTA
    int grid = (int)((n_qb + per_cta - 1) / per_cta);
    nf4_qdq_kernel<<<grid, NW * 32>>>(x, out, n_qb);
}

// round 9
// speedup vs baseline: 1.0113x; 1.0113x over previous
#include <cuda_runtime.h>

// NF4 blockwise quant-dequant (blocksize 512).
// One warp per 512-element quant block: 32 lanes x 16 elements (4x float4).
// R8 content, resubmitted after an infra-level bench failure (no signal).
// Cache-policy asymmetry: R3/R6/R7 all plateau at 37.3-38.6us kernel with
// HBM ~5.5TB/s; measured DRAM traffic (~212MB) < nominal (268MB) shows the
// re-read input partially persists in the 126MB L2 across graph replays.
//  - loads: DEFAULT policy (evict-normal) -> preserve cross-replay residency
//    (R6's __ldcs was evict-first on input and was *slower* than R3)
//  - stores: __stcs (evict-first) -> write-once output doesn't displace input
//  - pipeline removed (R7: +28 regs, occ -16pt, zero gain)

#define NQB_PER_CTA 8

// NF4 codebook (exact bitsandbytes constants)
#define C0  (-1.0f)
#define C1  (-0.6961928009986877f)
#define C2  (-0.5250730514526367f)
#define C3  (-0.39491748809814453f)
#define C4  (-0.28444138169288635f)
#define C5  (-0.18477343022823334f)
#define C6  (-0.09105003625154495f)
#define C7  (0.0f)
#define C8  (0.07958029955625534f)
#define C9  (0.16093020141124725f)
#define C10 (0.24611230194568634f)
#define C11 (0.33791524171829224f)
#define C12 (0.4407098591327667f)
#define C13 (0.5626170039176941f)
#define C14 (0.7229568362236023f)
#define C15 (1.0f)
// Decision boundaries: exact fp32 midpoints (folded at compile time, RN)
#define M0  ((C0  + C1 ) * 0.5f)
#define M1  ((C1  + C2 ) * 0.5f)
#define M2  ((C2  + C3 ) * 0.5f)
#define M3  ((C3  + C4 ) * 0.5f)
#define M4  ((C4  + C5 ) * 0.5f)
#define M5  ((C5  + C6 ) * 0.5f)
#define M6  ((C6  + C7 ) * 0.5f)
#define M7  ((C7  + C8 ) * 0.5f)
#define M8  ((C8  + C9 ) * 0.5f)
#define M9  ((C9  + C10) * 0.5f)
#define M10 ((C10 + C11) * 0.5f)
#define M11 ((C11 + C12) * 0.5f)
#define M12 ((C12 + C13) * 0.5f)
#define M13 ((C13 + C14) * 0.5f)
#define M14 ((C14 + C15) * 0.5f)
// "No boundary in this bucket" sentinel: huge finite fp32 (> any |x|).
#define SENT (3.0e38f)

// Bucket k covers xn in [k/16 - 1, (k+1)/16 - 1); width 1/16 < min boundary
// gap 0.0805 => at most one boundary per bucket.
// tbl[k] = { threshold (or SENT), codebook value at bucket start };
// value above the threshold == vlo of bucket k+1 (index j = k+1).
__device__ const float2 g_tbl[32] = {
    {SENT, C0 }, {SENT, C0 }, {M0,   C0 }, {SENT, C1 },
    {SENT, C1 }, {SENT, C1 }, {M1,   C1 }, {SENT, C2 },
    {M2,   C2 }, {SENT, C3 }, {M3,   C3 }, {SENT, C4 },
    {M4,   C4 }, {M5,   C5 }, {SENT, C6 }, {M6,   C6 },
    {M7,   C7 }, {M8,   C8 }, {SENT, C9 }, {M9,   C9 },
    {M10,  C10}, {SENT, C11}, {M11,  C11}, {SENT, C12},
    {M12,  C12}, {SENT, C13}, {M13,  C13}, {SENT, C14},
    {SENT, C14}, {M14,  C14}, {SENT, C15}, {SENT, C15}
};

__global__ __launch_bounds__(256) void nf4_qdq_kernel(
    const float* __restrict__ x, float* __restrict__ out, long long n_qb) {
    int warp = threadIdx.x >> 5;
    int lane = threadIdx.x & 31;
    long long qb = (long long)blockIdx.x * NQB_PER_CTA + warp;
    if (qb >= n_qb) return;   // warp-uniform; no barriers anywhere

    float2 te = g_tbl[lane];  // per-lane bucket entry, one 8B coalesced load

    const float4* __restrict__ in4  = (const float4*)(x   + qb * 512);
    float4*       __restrict__ out4 = (float4*)      (out + qb * 512);

    // 16 elements per lane, 4x coalesced 128-bit loads, DEFAULT cache policy
    // (keep input lines evict-normal in L2 for cross-replay reuse).
    float4 v[4];
    #pragma unroll
    for (int i = 0; i < 4; i++) v[i] = in4[i * 32 + lane];

    // Blockwise absmax: register FMNMX then warp butterfly (exact)
    float m = 0.0f;
    #pragma unroll
    for (int i = 0; i < 4; i++) {
        m = fmaxf(m, fabsf(v[i].x));
        m = fmaxf(m, fabsf(v[i].y));
        m = fmaxf(m, fabsf(v[i].z));
        m = fmaxf(m, fabsf(v[i].w));
    }
    #pragma unroll
    for (int s = 16; s; s >>= 1)
        m = fmaxf(m, __shfl_xor_sync(0xffffffffu, m, s));

    float absmax = m;
    float scale  = (absmax == 0.0f) ? 1.0f : absmax;
    float s16    = __frcp_rn(scale) * 16.0f;  // bucketing only; edge-tolerant

    // Scale into raw-x domain (once per warp; SENT*scale still > any |x|)
    float thr_s = te.x * scale;    // compare x > thr*scale  ~  x/scale > thr
    float vlo_s = te.y * absmax;   // same RN mul as reference NF4[idx]*absmax

    #pragma unroll
    for (int i = 0; i < 4; i++) {
        float4 r;
        #pragma unroll
        for (int e = 0; e < 4; e++) {
            float xv = (&v[i].x)[e];
            float kf = fmaf(xv, s16, 16.0f);       // bucket in [0,32]
            int k = min((int)kf, 31);              // trunc; -eps -> 0
            float t = __shfl_sync(0xffffffffu, thr_s, k);
            int j = k + ((xv > t) ? 1 : 0);        // above boundary -> next vlo
            (&r.x)[e] = __shfl_sync(0xffffffffu, vlo_s, j);
        }
        __stcs(&out4[i * 32 + lane], r);  // evict-first: don't pollute L2
    }
}

extern "C" void kernel_launch(void* const* d_in, const int* in_sizes, int n_in,
                              void* d_out, int out_size) {
    const float* x = (const float*)d_in[0];
    float* out = (float*)d_out;
    long long n = (long long)in_sizes[0];
    long long n_qb = n / 512;                 // n is a multiple of 512
    int grid = (int)((n_qb + NQB_PER_CTA - 1) / NQB_PER_CTA);
    nf4_qdq_kernel<<<grid, 256>>>(x, out, n_qb);
}